// round 1
// baseline (speedup 1.0000x reference)
#include <cuda_runtime.h>

#define BM 64
#define BN 64
#define DD 256
#define NTHREADS 256
#define NEG_BIG (-1e30f)

// smem (floats):
//  sQ  [256][64]  transposed+swizzled (s1*w3)
//  sKt [256][64]  transposed+swizzled s2 tile
//  sV  [64][256]  row-major s2 tile
//  sP  [64][65]   probabilities
//  sPart1[64], sPart2[1024]
#define SQ_OFF   0
#define SKT_OFF  (256*64)
#define SV_OFF   (2*256*64)
#define SP_OFF   (3*256*64)
#define SP1_OFF  (SP_OFF + 64*65)
#define SP2_OFF  (SP1_OFF + 64)
#define SMEM_FLOATS (SP2_OFF + 1024)

__global__ void __launch_bounds__(NTHREADS, 1)
bidaf_kernel(const float* __restrict__ s1, const float* __restrict__ s2,
             const float* __restrict__ w, const int* __restrict__ l1,
             const int* __restrict__ l2, float* __restrict__ out,
             int t1, int t2)
{
    extern __shared__ float sm[];
    float* sQ   = sm + SQ_OFF;
    float* sKt  = sm + SKT_OFF;
    float* sV   = sm + SV_OFF;
    float* sP   = sm + SP_OFF;
    float* sP1  = sm + SP1_OFF;
    float* sP2  = sm + SP2_OFF;

    const int b   = blockIdx.y;
    const int m0  = blockIdx.x * BM;
    const int tid = threadIdx.x;
    const int L1v = l1[b];
    const int L2v = l2[b];

    float* outTile = out + ((size_t)b * t1 + m0) * DD;

    if (m0 >= L1v || L2v == 0) {
        float4 z = make_float4(0.f, 0.f, 0.f, 0.f);
        #pragma unroll 4
        for (int i = tid; i < BM * DD / 4; i += NTHREADS)
            ((float4*)outTile)[i] = z;
        return;
    }

    const float* s1b = s1 + ((size_t)b * t1 + m0) * DD;
    const float* s2b = s2 + (size_t)b * t2 * DD;
    const float* w1 = w;
    const float* w2 = w + DD;
    const float* w3 = w + 2 * DD;

    const int ty = tid >> 4;        // 0..15  (row group of 4)
    const int tx = tid & 15;        // 0..15  (col group)

    // ---------- load Q tile: transpose, multiply by w3, swizzle ----------
    {
        const int rgrp = tid >> 6;          // 0..3
        const int c4   = tid & 63;          // float4 column within row
        const int sw   = 4 * (c4 & 15);     // swizzle for k = 4*c4..4*c4+3
        float4 w3v = ((const float4*)w3)[c4];
        const int k = 4 * c4;
        #pragma unroll
        for (int i = 0; i < 16; i++) {
            int m = i * 4 + rgrp;
            float4 v = ((const float4*)(s1b + m * DD))[c4];
            v.x *= w3v.x; v.y *= w3v.y; v.z *= w3v.z; v.w *= w3v.w;
            int mm = m ^ sw;
            sQ[(k + 0) * 64 + mm] = v.x;
            sQ[(k + 1) * 64 + mm] = v.y;
            sQ[(k + 2) * 64 + mm] = v.z;
            sQ[(k + 3) * 64 + mm] = v.w;
        }
    }

    // ---------- part1[m] = s1[m] . w1  (4 threads per row) ----------
    {
        const int r = tid >> 2;
        const int h = tid & 3;
        const float4* row = (const float4*)(s1b + r * DD);
        const float4* wv4 = (const float4*)w1;
        float acc = 0.f;
        #pragma unroll
        for (int q = 0; q < 16; q++) {
            int c = h * 16 + q;
            float4 a = row[c];
            float4 ww = wv4[c];
            acc += a.x * ww.x + a.y * ww.y + a.z * ww.z + a.w * ww.w;
        }
        acc += __shfl_xor_sync(0xffffffffu, acc, 1);
        acc += __shfl_xor_sync(0xffffffffu, acc, 2);
        if (h == 0) sP1[r] = acc;
    }

    // ---------- part2[n] = s2[n] . w2  for n < L2v ----------
    {
        const int r = tid >> 2;
        const int h = tid & 3;
        const float4* wv4 = (const float4*)w2;
        for (int nb = 0; nb < L2v; nb += 64) {
            int n = nb + r;
            const float4* row = (const float4*)(s2b + (size_t)n * DD);
            float acc = 0.f;
            #pragma unroll
            for (int q = 0; q < 16; q++) {
                int c = h * 16 + q;
                float4 a = row[c];
                float4 ww = wv4[c];
                acc += a.x * ww.x + a.y * ww.y + a.z * ww.z + a.w * ww.w;
            }
            acc += __shfl_xor_sync(0xffffffffu, acc, 1);
            acc += __shfl_xor_sync(0xffffffffu, acc, 2);
            if (h == 0) sP2[n] = (n < L2v) ? acc : 0.f;
        }
    }

    __syncthreads();

    // per-thread softmax / output state: rows 4*ty+i, out cols d = 4*tx + 64*q + e
    float mrow[4], lrow[4];
    float4 O[4][4];
    #pragma unroll
    for (int i = 0; i < 4; i++) {
        mrow[i] = -INFINITY;
        lrow[i] = 0.f;
        #pragma unroll
        for (int q = 0; q < 4; q++) O[i][q] = make_float4(0.f, 0.f, 0.f, 0.f);
    }

    const int ntiles = (L2v + BN - 1) / BN;
    for (int tI = 0; tI < ntiles; tI++) {
        const int n0 = tI * BN;

        // ---- load s2 tile: row-major into sV, transposed+swizzled into sKt ----
        {
            const int rgrp = tid >> 6;
            const int c4   = tid & 63;
            const int sw   = 4 * (c4 & 15);
            const int k    = 4 * c4;
            #pragma unroll
            for (int i = 0; i < 16; i++) {
                int n = i * 4 + rgrp;
                float4 v = ((const float4*)(s2b + (size_t)(n0 + n) * DD))[c4];
                ((float4*)(sV + n * DD))[c4] = v;
                int nn = n ^ sw;
                sKt[(k + 0) * 64 + nn] = v.x;
                sKt[(k + 1) * 64 + nn] = v.y;
                sKt[(k + 2) * 64 + nn] = v.z;
                sKt[(k + 3) * 64 + nn] = v.w;
            }
        }
        __syncthreads();

        // ---- score GEMM: S[64][64] = Q(64x256) * K(64x256)^T ----
        float c[4][4];
        #pragma unroll
        for (int i = 0; i < 4; i++)
            #pragma unroll
            for (int j = 0; j < 4; j++) c[i][j] = 0.f;

        const int ty4 = 4 * ty, tx4 = 4 * tx;
        #pragma unroll 4
        for (int k4 = 0; k4 < 64; k4++) {
            const int sw = 4 * (k4 & 15);
            const float* aB = sQ  + k4 * 256 + (ty4 ^ sw);
            const float* bB = sKt + k4 * 256 + (tx4 ^ sw);
            #pragma unroll
            for (int kk = 0; kk < 4; kk++) {
                float4 a  = *(const float4*)(aB + kk * 64);
                float4 bq = *(const float4*)(bB + kk * 64);
                c[0][0] += a.x * bq.x; c[0][1] += a.x * bq.y; c[0][2] += a.x * bq.z; c[0][3] += a.x * bq.w;
                c[1][0] += a.y * bq.x; c[1][1] += a.y * bq.y; c[1][2] += a.y * bq.z; c[1][3] += a.y * bq.w;
                c[2][0] += a.z * bq.x; c[2][1] += a.z * bq.y; c[2][2] += a.z * bq.z; c[2][3] += a.z * bq.w;
                c[3][0] += a.w * bq.x; c[3][1] += a.w * bq.y; c[3][2] += a.w * bq.z; c[3][3] += a.w * bq.w;
            }
        }

        // ---- bias + mask + online softmax ----
        #pragma unroll
        for (int i = 0; i < 4; i++) {
            const int lr = ty4 + i;               // local row
            const float p1v = sP1[lr];
            float rowm = -INFINITY;
            #pragma unroll
            for (int j = 0; j < 4; j++) {
                const int gc = n0 + tx4 + j;
                float sc = c[i][j] + p1v + sP2[gc];
                sc = (gc < L2v) ? sc : NEG_BIG;
                c[i][j] = sc;
                rowm = fmaxf(rowm, sc);
            }
            rowm = fmaxf(rowm, __shfl_xor_sync(0xffffffffu, rowm, 1));
            rowm = fmaxf(rowm, __shfl_xor_sync(0xffffffffu, rowm, 2));
            rowm = fmaxf(rowm, __shfl_xor_sync(0xffffffffu, rowm, 4));
            rowm = fmaxf(rowm, __shfl_xor_sync(0xffffffffu, rowm, 8));

            const float mnew  = fmaxf(mrow[i], rowm);
            const float alpha = __expf(mrow[i] - mnew);
            mrow[i] = mnew;

            float ls = 0.f;
            #pragma unroll
            for (int j = 0; j < 4; j++) {
                float p = __expf(c[i][j] - mnew);
                sP[lr * 65 + tx4 + j] = p;
                ls += p;
            }
            ls += __shfl_xor_sync(0xffffffffu, ls, 1);
            ls += __shfl_xor_sync(0xffffffffu, ls, 2);
            ls += __shfl_xor_sync(0xffffffffu, ls, 4);
            ls += __shfl_xor_sync(0xffffffffu, ls, 8);
            lrow[i] = lrow[i] * alpha + ls;

            #pragma unroll
            for (int q = 0; q < 4; q++) {
                O[i][q].x *= alpha; O[i][q].y *= alpha;
                O[i][q].z *= alpha; O[i][q].w *= alpha;
            }
        }
        __syncthreads();

        // ---- PV GEMM: O[64][256] += P[64][64] * V[64][256] ----
        #pragma unroll 2
        for (int n = 0; n < BN; n++) {
            const float p0 = sP[(ty4 + 0) * 65 + n];
            const float p1 = sP[(ty4 + 1) * 65 + n];
            const float p2 = sP[(ty4 + 2) * 65 + n];
            const float p3 = sP[(ty4 + 3) * 65 + n];
            const float* vrow = sV + n * DD + tx4;
            #pragma unroll
            for (int q = 0; q < 4; q++) {
                float4 v = *(const float4*)(vrow + 64 * q);
                O[0][q].x += p0 * v.x; O[0][q].y += p0 * v.y; O[0][q].z += p0 * v.z; O[0][q].w += p0 * v.w;
                O[1][q].x += p1 * v.x; O[1][q].y += p1 * v.y; O[1][q].z += p1 * v.z; O[1][q].w += p1 * v.w;
                O[2][q].x += p2 * v.x; O[2][q].y += p2 * v.y; O[2][q].z += p2 * v.z; O[2][q].w += p2 * v.w;
                O[3][q].x += p3 * v.x; O[3][q].y += p3 * v.y; O[3][q].z += p3 * v.z; O[3][q].w += p3 * v.w;
            }
        }
        __syncthreads();
    }

    // ---------- finalize: divide by l, zero masked rows, write ----------
    #pragma unroll
    for (int i = 0; i < 4; i++) {
        const int gr = m0 + 4 * ty + i;
        const bool valid = (gr < L1v) && (lrow[i] > 0.f);
        const float inv = valid ? (1.f / lrow[i]) : 0.f;
        float* orow = outTile + (4 * ty + i) * DD + 4 * tx;
        #pragma unroll
        for (int q = 0; q < 4; q++) {
            float4 o = O[i][q];
            o.x *= inv; o.y *= inv; o.z *= inv; o.w *= inv;
            *(float4*)(orow + 64 * q) = o;
        }
    }
}

extern "C" void kernel_launch(void* const* d_in, const int* in_sizes, int n_in,
                              void* d_out, int out_size)
{
    const float* s1 = (const float*)d_in[0];
    const float* s2 = (const float*)d_in[1];
    const float* w  = (const float*)d_in[2];
    const int*   l1 = (const int*)d_in[3];
    const int*   l2 = (const int*)d_in[4];
    float* out = (float*)d_out;

    const int B  = in_sizes[3];
    const int D  = in_sizes[2] / 3;          // 256
    const int t1 = in_sizes[0] / (B * D);    // 1024
    const int t2 = in_sizes[1] / (B * D);    // 1024

    const size_t smem = SMEM_FLOATS * sizeof(float);
    cudaFuncSetAttribute(bidaf_kernel,
                         cudaFuncAttributeMaxDynamicSharedMemorySize, (int)smem);

    dim3 grid(t1 / BM, B);
    bidaf_kernel<<<grid, NTHREADS, smem>>>(s1, s2, w, l1, l2, out, t1, t2);
}

// round 4
// speedup vs baseline: 1.9877x; 1.9877x over previous
#include <cuda_runtime.h>
#include <cuda_bf16.h>
#include <cstdint>

#define NT 256
#define DD 256
#define NEG_BIG (-1e30f)

// ---- smem byte offsets (from 128B-aligned base) ----
#define QHI_OFF 0          // [64][256] bf16, 512B/row, swizzled
#define QLO_OFF 32768
#define KHI_OFF 65536      // [64][256] bf16 (K and V view of s2 tile)
#define KLO_OFF 98304
#define PHI_OFF 131072     // [64][64] bf16, 128B/row, swizzled
#define PLO_OFF 139264
#define P1_OFF  147456     // 64 f32
#define P2_OFF  147712     // 64 f32
#define HM_OFF  147968     // [64][2] f32 half-maxes
#define HS_OFF  148480     // [64][2] f32 half-sums
#define SMEM_USED 148992
#define SMEM_BYTES (SMEM_USED + 128)

__device__ __forceinline__ uint32_t smem_u32(const void* p) {
    uint32_t a;
    asm("{ .reg .u64 t; cvta.to.shared.u64 t, %1; cvt.u32.u64 %0, t; }"
        : "=r"(a) : "l"(p));
    return a;
}

__device__ __forceinline__ void ldsm_x4(uint32_t& a0, uint32_t& a1, uint32_t& a2,
                                        uint32_t& a3, uint32_t addr) {
    asm volatile("ldmatrix.sync.aligned.m8n8.x4.shared.b16 {%0,%1,%2,%3}, [%4];"
                 : "=r"(a0), "=r"(a1), "=r"(a2), "=r"(a3) : "r"(addr));
}
__device__ __forceinline__ void ldsm_x2(uint32_t& b0, uint32_t& b1, uint32_t addr) {
    asm volatile("ldmatrix.sync.aligned.m8n8.x2.shared.b16 {%0,%1}, [%2];"
                 : "=r"(b0), "=r"(b1) : "r"(addr));
}
__device__ __forceinline__ void ldsm_x2t(uint32_t& b0, uint32_t& b1, uint32_t addr) {
    asm volatile("ldmatrix.sync.aligned.m8n8.x2.trans.shared.b16 {%0,%1}, [%2];"
                 : "=r"(b0), "=r"(b1) : "r"(addr));
}
__device__ __forceinline__ void mma16816(float* c, uint32_t a0, uint32_t a1,
                                         uint32_t a2, uint32_t a3,
                                         uint32_t b0, uint32_t b1) {
    asm volatile(
        "mma.sync.aligned.m16n8k16.row.col.f32.bf16.bf16.f32 "
        "{%0,%1,%2,%3}, {%4,%5,%6,%7}, {%8,%9}, {%0,%1,%2,%3};"
        : "+f"(c[0]), "+f"(c[1]), "+f"(c[2]), "+f"(c[3])
        : "r"(a0), "r"(a1), "r"(a2), "r"(a3), "r"(b0), "r"(b1));
}

// swizzled chunk address: 16B chunks, XOR low-3 chunk bits with row&7
__device__ __forceinline__ uint32_t swz(int row, int chunk, int rowbytes) {
    int c = (chunk & ~7) | ((chunk & 7) ^ (row & 7));
    return (uint32_t)(row * rowbytes + c * 16);
}

// split 2 floats into packed bf16 hi + residual lo
__device__ __forceinline__ void split2(float a, float b, uint32_t& hi, uint32_t& lo) {
    __nv_bfloat16 ha = __float2bfloat16(a), hb = __float2bfloat16(b);
    float ra = a - __bfloat162float(ha), rb = b - __bfloat162float(hb);
    __nv_bfloat162 h; h.x = ha; h.y = hb;
    __nv_bfloat162 l; l.x = __float2bfloat16(ra); l.y = __float2bfloat16(rb);
    hi = *(uint32_t*)&h; lo = *(uint32_t*)&l;
}

__global__ void __launch_bounds__(NT, 1)
bidaf_mma(const float* __restrict__ s1, const float* __restrict__ s2,
          const float* __restrict__ w, const int* __restrict__ l1,
          const int* __restrict__ l2, float* __restrict__ out)
{
    extern __shared__ char sm_raw[];
    char* smc = (char*)(((uintptr_t)sm_raw + 127) & ~(uintptr_t)127);

    const int b   = blockIdx.y;
    const int m0  = blockIdx.x * 64;
    const int tid = threadIdx.x;
    const int L1v = l1[b], L2v = l2[b];
    float* outTile = out + ((size_t)b * 1024 + m0) * DD;

    if (m0 >= L1v || L2v == 0) {
        float4 z = make_float4(0.f, 0.f, 0.f, 0.f);
        for (int i = tid; i < 64 * DD / 4; i += NT) ((float4*)outTile)[i] = z;
        return;
    }

    const uint32_t smem = smem_u32(smc);
    const int lane = tid & 31;
    const int wid  = tid >> 5;
    const int rg   = wid >> 1;   // row group 0..3 (16 rows each)
    const int ch   = wid & 1;    // col half (score: 32 n-cols; PV: 128 d-cols)

    const float* s1b = s1 + ((size_t)b * 1024 + m0) * DD;
    const float* s2b = s2 + (size_t)b * 1024 * DD;
    const float4* w1v = (const float4*)w;
    const float4* w2v = (const float4*)(w + DD);
    const float4* w3v = (const float4*)(w + 2 * DD);

    // ---------------- prologue: Q = s1*w3 -> bf16 hi/lo smem; part1 ----------------
    {
        const int row = tid >> 2, h = tid & 3;
        const float4* qr = (const float4*)(s1b + row * DD);
        float acc = 0.f;
        #pragma unroll
        for (int cc = 0; cc < 8; cc++) {
            int c4 = h * 16 + cc * 2;   // float4 index (2 per 16B-bf16 chunk)
            float4 v0 = qr[c4], v1 = qr[c4 + 1];
            float4 a0 = w1v[c4], a1 = w1v[c4 + 1];
            acc += v0.x * a0.x + v0.y * a0.y + v0.z * a0.z + v0.w * a0.w;
            acc += v1.x * a1.x + v1.y * a1.y + v1.z * a1.z + v1.w * a1.w;
            float4 m3a = w3v[c4], m3b = w3v[c4 + 1];
            float q0 = v0.x * m3a.x, q1 = v0.y * m3a.y, q2 = v0.z * m3a.z, q3 = v0.w * m3a.w;
            float q4 = v1.x * m3b.x, q5 = v1.y * m3b.y, q6 = v1.z * m3b.z, q7 = v1.w * m3b.w;
            uint4 hi, lo;
            split2(q0, q1, hi.x, lo.x); split2(q2, q3, hi.y, lo.y);
            split2(q4, q5, hi.z, lo.z); split2(q6, q7, hi.w, lo.w);
            uint32_t off = swz(row, h * 8 + cc, 512);
            *(uint4*)(smc + QHI_OFF + off) = hi;
            *(uint4*)(smc + QLO_OFF + off) = lo;
        }
        acc += __shfl_xor_sync(0xffffffffu, acc, 1);
        acc += __shfl_xor_sync(0xffffffffu, acc, 2);
        if (h == 0) ((float*)(smc + P1_OFF))[row] = acc;
    }
    __syncthreads();

    const int r0l = rg * 16 + (lane >> 2);   // local row of c-frag rows 0..7
    const float p1a = ((const float*)(smc + P1_OFF))[r0l];
    const float p1b = ((const float*)(smc + P1_OFF))[r0l + 8];

    float O[16][4];
    #pragma unroll
    for (int j = 0; j < 16; j++)
        #pragma unroll
        for (int e = 0; e < 4; e++) O[j][e] = 0.f;
    float mrow0 = -INFINITY, mrow1 = -INFINITY, lrow0 = 0.f, lrow1 = 0.f;

    float* hm = (float*)(smc + HM_OFF);
    float* hs = (float*)(smc + HS_OFF);

    const int ntiles = (L2v + 63) >> 6;
    for (int t = 0; t < ntiles; t++) {
        const int n0 = t * 64;
        __syncthreads();   // prior PV done with K/P smem

        // ---- load s2 tile -> bf16 hi/lo; part2 ----
        {
            const int n = tid >> 2, h = tid & 3;
            const float4* kr = (const float4*)(s2b + (size_t)(n0 + n) * DD);
            float acc = 0.f;
            #pragma unroll
            for (int cc = 0; cc < 8; cc++) {
                int c4 = h * 16 + cc * 2;
                float4 v0 = kr[c4], v1 = kr[c4 + 1];
                float4 a0 = w2v[c4], a1 = w2v[c4 + 1];
                acc += v0.x * a0.x + v0.y * a0.y + v0.z * a0.z + v0.w * a0.w;
                acc += v1.x * a1.x + v1.y * a1.y + v1.z * a1.z + v1.w * a1.w;
                uint4 hi, lo;
                split2(v0.x, v0.y, hi.x, lo.x); split2(v0.z, v0.w, hi.y, lo.y);
                split2(v1.x, v1.y, hi.z, lo.z); split2(v1.z, v1.w, hi.w, lo.w);
                uint32_t off = swz(n, h * 8 + cc, 512);
                *(uint4*)(smc + KHI_OFF + off) = hi;
                *(uint4*)(smc + KLO_OFF + off) = lo;
            }
            acc += __shfl_xor_sync(0xffffffffu, acc, 1);
            acc += __shfl_xor_sync(0xffffffffu, acc, 2);
            if (h == 0) ((float*)(smc + P2_OFF))[n] = acc;
        }
        __syncthreads();

        // ---- score GEMM: S[16 rows][32 cols] per warp, 3-term bf16 split ----
        float c[4][4];
        #pragma unroll
        for (int j = 0; j < 4; j++)
            #pragma unroll
            for (int e = 0; e < 4; e++) c[j][e] = 0.f;

        const int arow = rg * 16 + (lane & 15);
        const int brow0 = ch * 32 + (lane & 7);
        #pragma unroll 4
        for (int k16 = 0; k16 < 16; k16++) {
            uint32_t aoff = swz(arow, 2 * k16 + (lane >> 4), 512);
            uint32_t ah0, ah1, ah2, ah3, al0, al1, al2, al3;
            ldsm_x4(ah0, ah1, ah2, ah3, smem + QHI_OFF + aoff);
            ldsm_x4(al0, al1, al2, al3, smem + QLO_OFF + aoff);
            #pragma unroll
            for (int j = 0; j < 4; j++) {
                uint32_t boff = swz(brow0 + j * 8, 2 * k16 + ((lane >> 3) & 1), 512);
                uint32_t bh0, bh1, bl0, bl1;
                ldsm_x2(bh0, bh1, smem + KHI_OFF + boff);
                ldsm_x2(bl0, bl1, smem + KLO_OFF + boff);
                mma16816(c[j], ah0, ah1, ah2, ah3, bh0, bh1);
                mma16816(c[j], ah0, ah1, ah2, ah3, bl0, bl1);
                mma16816(c[j], al0, al1, al2, al3, bh0, bh1);
            }
        }

        // ---- bias + mask + row max ----
        const float* p2f = (const float*)(smc + P2_OFF);
        float mx0 = -INFINITY, mx1 = -INFINITY;
        #pragma unroll
        for (int j = 0; j < 4; j++) {
            #pragma unroll
            for (int e = 0; e < 2; e++) {
                int col = ch * 32 + j * 8 + 2 * (lane & 3) + e;
                bool valid = (n0 + col) < L2v;
                float bias = p2f[col];
                float s0 = c[j][e] + p1a + bias;
                float s1v = c[j][e + 2] + p1b + bias;
                s0 = valid ? s0 : NEG_BIG;
                s1v = valid ? s1v : NEG_BIG;
                c[j][e] = s0; c[j][e + 2] = s1v;
                mx0 = fmaxf(mx0, s0); mx1 = fmaxf(mx1, s1v);
            }
        }
        mx0 = fmaxf(mx0, __shfl_xor_sync(0xffffffffu, mx0, 1));
        mx0 = fmaxf(mx0, __shfl_xor_sync(0xffffffffu, mx0, 2));
        mx1 = fmaxf(mx1, __shfl_xor_sync(0xffffffffu, mx1, 1));
        mx1 = fmaxf(mx1, __shfl_xor_sync(0xffffffffu, mx1, 2));
        if ((lane & 3) == 0) {
            hm[r0l * 2 + ch] = mx0;
            hm[(r0l + 8) * 2 + ch] = mx1;
        }
        __syncthreads();

        const float tm0 = fmaxf(hm[r0l * 2], hm[r0l * 2 + 1]);
        const float tm1 = fmaxf(hm[(r0l + 8) * 2], hm[(r0l + 8) * 2 + 1]);
        const float mnew0 = fmaxf(mrow0, tm0), mnew1 = fmaxf(mrow1, tm1);
        const float alpha0 = __expf(mrow0 - mnew0), alpha1 = __expf(mrow1 - mnew1);
        mrow0 = mnew0; mrow1 = mnew1;

        float sum0 = 0.f, sum1 = 0.f;
        #pragma unroll
        for (int j = 0; j < 4; j++) {
            float p00 = __expf(c[j][0] - mnew0), p01 = __expf(c[j][1] - mnew0);
            float p10 = __expf(c[j][2] - mnew1), p11 = __expf(c[j][3] - mnew1);
            sum0 += p00 + p01; sum1 += p10 + p11;
            // write P hi/lo to smem
            int nloc = ch * 32 + j * 8 + 2 * (lane & 3);
            int chunk = nloc >> 3;
            uint32_t hi, lo;
            uint32_t off0 = (uint32_t)(r0l * 128 + ((chunk ^ (r0l & 7)) * 16) + (nloc & 7) * 2);
            split2(p00, p01, hi, lo);
            *(uint32_t*)(smc + PHI_OFF + off0) = hi;
            *(uint32_t*)(smc + PLO_OFF + off0) = lo;
            int r1 = r0l + 8;
            uint32_t off1 = (uint32_t)(r1 * 128 + ((chunk ^ (r1 & 7)) * 16) + (nloc & 7) * 2);
            split2(p10, p11, hi, lo);
            *(uint32_t*)(smc + PHI_OFF + off1) = hi;
            *(uint32_t*)(smc + PLO_OFF + off1) = lo;
        }
        sum0 += __shfl_xor_sync(0xffffffffu, sum0, 1);
        sum0 += __shfl_xor_sync(0xffffffffu, sum0, 2);
        sum1 += __shfl_xor_sync(0xffffffffu, sum1, 1);
        sum1 += __shfl_xor_sync(0xffffffffu, sum1, 2);
        if ((lane & 3) == 0) {
            hs[r0l * 2 + ch] = sum0;
            hs[(r0l + 8) * 2 + ch] = sum1;
        }

        // rescale O while sums land
        #pragma unroll
        for (int j = 0; j < 16; j++) {
            O[j][0] *= alpha0; O[j][1] *= alpha0;
            O[j][2] *= alpha1; O[j][3] *= alpha1;
        }
        __syncthreads();

        lrow0 = lrow0 * alpha0 + hs[r0l * 2] + hs[r0l * 2 + 1];
        lrow1 = lrow1 * alpha1 + hs[(r0l + 8) * 2] + hs[(r0l + 8) * 2 + 1];

        // ---- PV GEMM: O[16 rows][128 d] += P[16][64] * V[64][128] ----
        #pragma unroll
        for (int ks = 0; ks < 4; ks++) {
            uint32_t aoff = swz(rg * 16 + (lane & 15), 2 * ks + (lane >> 4), 128);
            uint32_t ph0, ph1, ph2, ph3, pl0, pl1, pl2, pl3;
            ldsm_x4(ph0, ph1, ph2, ph3, smem + PHI_OFF + aoff);
            ldsm_x4(pl0, pl1, pl2, pl3, smem + PLO_OFF + aoff);
            const int vrow = ks * 16 + (lane & 15);
            #pragma unroll
            for (int j = 0; j < 16; j++) {
                uint32_t boff = swz(vrow, ch * 16 + j, 512);
                uint32_t vh0, vh1, vl0, vl1;
                ldsm_x2t(vh0, vh1, smem + KHI_OFF + boff);
                ldsm_x2t(vl0, vl1, smem + KLO_OFF + boff);
                mma16816(O[j], ph0, ph1, ph2, ph3, vh0, vh1);
                mma16816(O[j], ph0, ph1, ph2, ph3, vl0, vl1);
                mma16816(O[j], pl0, pl1, pl2, pl3, vh0, vh1);
            }
        }
    }

    // ---------------- epilogue ----------------
    const int gr0 = m0 + r0l, gr1 = gr0 + 8;
    const float inv0 = (gr0 < L1v) ? (1.f / lrow0) : 0.f;
    const float inv1 = (gr1 < L1v) ? (1.f / lrow1) : 0.f;
    float* orow0 = outTile + r0l * DD + ch * 128 + 2 * (lane & 3);
    float* orow1 = orow0 + 8 * DD;
    #pragma unroll
    for (int j = 0; j < 16; j++) {
        float2 v0; v0.x = O[j][0] * inv0; v0.y = O[j][1] * inv0;
        float2 v1; v1.x = O[j][2] * inv1; v1.y = O[j][3] * inv1;
        *(float2*)(orow0 + j * 8) = v0;
        *(float2*)(orow1 + j * 8) = v1;
    }
}

extern "C" void kernel_launch(void* const* d_in, const int* in_sizes, int n_in,
                              void* d_out, int out_size)
{
    const float* s1 = (const float*)d_in[0];
    const float* s2 = (const float*)d_in[1];
    const float* w  = (const float*)d_in[2];
    const int*   l1 = (const int*)d_in[3];
    const int*   l2 = (const int*)d_in[4];
    float* out = (float*)d_out;

    const int B  = in_sizes[3];
    const int D  = in_sizes[2] / 3;
    const int t1 = in_sizes[0] / (B * D);

    cudaFuncSetAttribute(bidaf_mma, cudaFuncAttributeMaxDynamicSharedMemorySize,
                         SMEM_BYTES);
    dim3 grid(t1 / 64, B);
    bidaf_mma<<<grid, NT, SMEM_BYTES>>>(s1, s2, w, l1, l2, out);
}

// round 5
// speedup vs baseline: 2.1556x; 1.0844x over previous
#include <cuda_runtime.h>
#include <cuda_bf16.h>
#include <cstdint>

#define NT 256
#define DD 256
#define NEG_BIG (-1e30f)

// ---- smem byte offsets (from 128B-aligned base) ----
#define QHI_OFF 0          // [64][256] bf16, 512B/row, swizzled
#define QLO_OFF 32768
#define KHI_OFF 65536      // [64][256] bf16 (K and V view of s2 tile)
#define KLO_OFF 98304
#define RAW_OFF 131072     // [64][256] f32 raw prefetch buffer (64KB)
#define PHI_OFF 196608     // [64][64] bf16, 128B/row, swizzled
#define PLO_OFF 204800
#define P1_OFF  212992     // 64 f32
#define P2_OFF  213248     // 64 f32
#define HM_OFF  213504     // [64][2] f32 half-maxes
#define HS_OFF  214016     // [64][2] f32 half-sums
#define SMEM_USED 214528
#define SMEM_BYTES (SMEM_USED + 128)

__device__ __forceinline__ uint32_t smem_u32(const void* p) {
    uint32_t a;
    asm("{ .reg .u64 t; cvta.to.shared.u64 t, %1; cvt.u32.u64 %0, t; }"
        : "=r"(a) : "l"(p));
    return a;
}

#define CP_ASYNC16(dst, src) \
    asm volatile("cp.async.cg.shared.global [%0], [%1], 16;" \
        :: "r"(dst), "l"(src) : "memory")
#define CP_COMMIT() asm volatile("cp.async.commit_group;" ::: "memory")
#define CP_WAIT0()  asm volatile("cp.async.wait_group 0;" ::: "memory")

__device__ __forceinline__ void ldsm_x4(uint32_t& a0, uint32_t& a1, uint32_t& a2,
                                        uint32_t& a3, uint32_t addr) {
    asm volatile("ldmatrix.sync.aligned.m8n8.x4.shared.b16 {%0,%1,%2,%3}, [%4];"
                 : "=r"(a0), "=r"(a1), "=r"(a2), "=r"(a3) : "r"(addr));
}
__device__ __forceinline__ void ldsm_x4t(uint32_t& a0, uint32_t& a1, uint32_t& a2,
                                         uint32_t& a3, uint32_t addr) {
    asm volatile("ldmatrix.sync.aligned.m8n8.x4.trans.shared.b16 {%0,%1,%2,%3}, [%4];"
                 : "=r"(a0), "=r"(a1), "=r"(a2), "=r"(a3) : "r"(addr));
}
__device__ __forceinline__ void mma16816(float* c, uint32_t a0, uint32_t a1,
                                         uint32_t a2, uint32_t a3,
                                         uint32_t b0, uint32_t b1) {
    asm volatile(
        "mma.sync.aligned.m16n8k16.row.col.f32.bf16.bf16.f32 "
        "{%0,%1,%2,%3}, {%4,%5,%6,%7}, {%8,%9}, {%0,%1,%2,%3};"
        : "+f"(c[0]), "+f"(c[1]), "+f"(c[2]), "+f"(c[3])
        : "r"(a0), "r"(a1), "r"(a2), "r"(a3), "r"(b0), "r"(b1));
}

// swizzled chunk address: 16B chunks, XOR low-3 chunk bits with row&7
__device__ __forceinline__ uint32_t swz(int row, int chunk, int rowbytes) {
    int c = (chunk & ~7) | ((chunk & 7) ^ (row & 7));
    return (uint32_t)(row * rowbytes + c * 16);
}

// split 2 floats into packed bf16 hi + residual lo
__device__ __forceinline__ void split2(float a, float b, uint32_t& hi, uint32_t& lo) {
    __nv_bfloat16 ha = __float2bfloat16(a), hb = __float2bfloat16(b);
    float ra = a - __bfloat162float(ha), rb = b - __bfloat162float(hb);
    __nv_bfloat162 h; h.x = ha; h.y = hb;
    __nv_bfloat162 l; l.x = __float2bfloat16(ra); l.y = __float2bfloat16(rb);
    hi = *(uint32_t*)&h; lo = *(uint32_t*)&l;
}

__global__ void __launch_bounds__(NT, 1)
bidaf_mma(const float* __restrict__ s1, const float* __restrict__ s2,
          const float* __restrict__ w, const int* __restrict__ l1,
          const int* __restrict__ l2, float* __restrict__ out)
{
    extern __shared__ char sm_raw[];
    char* smc = (char*)(((uintptr_t)sm_raw + 127) & ~(uintptr_t)127);

    const int b   = blockIdx.y;
    const int m0  = blockIdx.x * 64;
    const int tid = threadIdx.x;
    const int L1v = l1[b], L2v = l2[b];
    float* outTile = out + ((size_t)b * 1024 + m0) * DD;

    if (m0 >= L1v || L2v == 0) {
        float4 z = make_float4(0.f, 0.f, 0.f, 0.f);
        for (int i = tid; i < 64 * DD / 4; i += NT) ((float4*)outTile)[i] = z;
        return;
    }

    const uint32_t smem = smem_u32(smc);
    const int lane = tid & 31;
    const int wid  = tid >> 5;
    const int rg   = wid >> 1;   // row group 0..3 (16 rows each)
    const int ch   = wid & 1;    // col half

    const float* s1b = s1 + ((size_t)b * 1024 + m0) * DD;
    const float* s2b = s2 + (size_t)b * 1024 * DD;
    const float4* w1v = (const float4*)w;
    const float4* w2v = (const float4*)(w + DD);
    const float4* w3v = (const float4*)(w + 2 * DD);

    const int prow = tid >> 2, ph = tid & 3;   // prefetch/convert mapping

    // ---- prefetch tile 0 into RAW (overlaps the Q prologue below) ----
    {
        const char* src = (const char*)(s2b + (size_t)prow * DD);
        uint32_t dst = smem + RAW_OFF + (uint32_t)prow * 1024;
        #pragma unroll
        for (int i = 0; i < 16; i++) {
            int c = ph * 16 + i;
            CP_ASYNC16(dst + c * 16, src + c * 16);
        }
        CP_COMMIT();
    }

    // ---------------- prologue: Q = s1*w3 -> bf16 hi/lo smem; part1 ----------------
    {
        const float4* qr = (const float4*)(s1b + prow * DD);
        float acc = 0.f;
        #pragma unroll
        for (int cc = 0; cc < 8; cc++) {
            int c4 = ph * 16 + cc * 2;
            float4 v0 = qr[c4], v1 = qr[c4 + 1];
            float4 a0 = w1v[c4], a1 = w1v[c4 + 1];
            acc += v0.x * a0.x + v0.y * a0.y + v0.z * a0.z + v0.w * a0.w;
            acc += v1.x * a1.x + v1.y * a1.y + v1.z * a1.z + v1.w * a1.w;
            float4 m3a = w3v[c4], m3b = w3v[c4 + 1];
            float q0 = v0.x * m3a.x, q1 = v0.y * m3a.y, q2 = v0.z * m3a.z, q3 = v0.w * m3a.w;
            float q4 = v1.x * m3b.x, q5 = v1.y * m3b.y, q6 = v1.z * m3b.z, q7 = v1.w * m3b.w;
            uint4 hi, lo;
            split2(q0, q1, hi.x, lo.x); split2(q2, q3, hi.y, lo.y);
            split2(q4, q5, hi.z, lo.z); split2(q6, q7, hi.w, lo.w);
            uint32_t off = swz(prow, ph * 8 + cc, 512);
            *(uint4*)(smc + QHI_OFF + off) = hi;
            *(uint4*)(smc + QLO_OFF + off) = lo;
        }
        acc += __shfl_xor_sync(0xffffffffu, acc, 1);
        acc += __shfl_xor_sync(0xffffffffu, acc, 2);
        if (ph == 0) ((float*)(smc + P1_OFF))[prow] = acc;
    }
    __syncthreads();

    const int r0l = rg * 16 + (lane >> 2);   // c-frag rows
    const float p1a = ((const float*)(smc + P1_OFF))[r0l];
    const float p1b = ((const float*)(smc + P1_OFF))[r0l + 8];

    float O[16][4];
    #pragma unroll
    for (int j = 0; j < 16; j++)
        #pragma unroll
        for (int e = 0; e < 4; e++) O[j][e] = 0.f;
    float mrow0 = -INFINITY, mrow1 = -INFINITY, lrow0 = 0.f, lrow1 = 0.f;

    float* hm = (float*)(smc + HM_OFF);
    float* hs = (float*)(smc + HS_OFF);
    const float4* rawv = (const float4*)(smc + RAW_OFF);

    const int ntiles = (L2v + 63) >> 6;
    for (int t = 0; t < ntiles; t++) {
        const int n0 = t * 64;

        CP_WAIT0();
        __syncthreads();   // raw tile ready; prior PV done with K/P smem

        // ---- convert raw f32 -> K bf16 hi/lo; part2 ----
        {
            float acc = 0.f;
            #pragma unroll
            for (int cc = 0; cc < 8; cc++) {
                int c4 = cc * 8 + ph * 2;            // bank-conflict-free read
                float4 v0 = rawv[prow * 64 + c4], v1 = rawv[prow * 64 + c4 + 1];
                float4 a0 = w2v[c4], a1 = w2v[c4 + 1];
                acc += v0.x * a0.x + v0.y * a0.y + v0.z * a0.z + v0.w * a0.w;
                acc += v1.x * a1.x + v1.y * a1.y + v1.z * a1.z + v1.w * a1.w;
                uint4 hi, lo;
                split2(v0.x, v0.y, hi.x, lo.x); split2(v0.z, v0.w, hi.y, lo.y);
                split2(v1.x, v1.y, hi.z, lo.z); split2(v1.z, v1.w, hi.w, lo.w);
                uint32_t off = swz(prow, cc * 4 + ph, 512);
                *(uint4*)(smc + KHI_OFF + off) = hi;
                *(uint4*)(smc + KLO_OFF + off) = lo;
            }
            acc += __shfl_xor_sync(0xffffffffu, acc, 1);
            acc += __shfl_xor_sync(0xffffffffu, acc, 2);
            if (ph == 0) ((float*)(smc + P2_OFF))[prow] = acc;
        }
        __syncthreads();   // K hi/lo + P2 ready; raw consumed

        // ---- prefetch next tile ----
        if (t + 1 < ntiles) {
            const char* src = (const char*)(s2b + (size_t)(n0 + 64 + prow) * DD);
            uint32_t dst = smem + RAW_OFF + (uint32_t)prow * 1024;
            #pragma unroll
            for (int i = 0; i < 16; i++) {
                int c = ph * 16 + i;
                CP_ASYNC16(dst + c * 16, src + c * 16);
            }
            CP_COMMIT();
        }

        // ---- score GEMM: S[16 rows][32 cols] per warp, 3-term bf16 split ----
        float c[4][4];
        #pragma unroll
        for (int j = 0; j < 4; j++)
            #pragma unroll
            for (int e = 0; e < 4; e++) c[j][e] = 0.f;

        const int arow = rg * 16 + (lane & 15);
        const int brow = ch * 32 + (lane & 7) + ((lane >> 4) & 1) * 8;
        #pragma unroll 4
        for (int k16 = 0; k16 < 16; k16++) {
            uint32_t aoff = swz(arow, 2 * k16 + (lane >> 4), 512);
            uint32_t ah0, ah1, ah2, ah3, al0, al1, al2, al3;
            ldsm_x4(ah0, ah1, ah2, ah3, smem + QHI_OFF + aoff);
            ldsm_x4(al0, al1, al2, al3, smem + QLO_OFF + aoff);
            #pragma unroll
            for (int jp = 0; jp < 2; jp++) {
                uint32_t boff = swz(brow + jp * 16, 2 * k16 + ((lane >> 3) & 1), 512);
                uint32_t bh0, bh1, bh2, bh3, bl0, bl1, bl2, bl3;
                ldsm_x4(bh0, bh1, bh2, bh3, smem + KHI_OFF + boff);
                ldsm_x4(bl0, bl1, bl2, bl3, smem + KLO_OFF + boff);
                mma16816(c[2 * jp], ah0, ah1, ah2, ah3, bh0, bh1);
                mma16816(c[2 * jp + 1], ah0, ah1, ah2, ah3, bh2, bh3);
                mma16816(c[2 * jp], ah0, ah1, ah2, ah3, bl0, bl1);
                mma16816(c[2 * jp + 1], ah0, ah1, ah2, ah3, bl2, bl3);
                mma16816(c[2 * jp], al0, al1, al2, al3, bh0, bh1);
                mma16816(c[2 * jp + 1], al0, al1, al2, al3, bh2, bh3);
            }
        }

        // ---- bias + mask + row max ----
        const float* p2f = (const float*)(smc + P2_OFF);
        float mx0 = -INFINITY, mx1 = -INFINITY;
        #pragma unroll
        for (int j = 0; j < 4; j++) {
            #pragma unroll
            for (int e = 0; e < 2; e++) {
                int col = ch * 32 + j * 8 + 2 * (lane & 3) + e;
                bool valid = (n0 + col) < L2v;
                float bias = p2f[col];
                float s0 = c[j][e] + p1a + bias;
                float s1v = c[j][e + 2] + p1b + bias;
                s0 = valid ? s0 : NEG_BIG;
                s1v = valid ? s1v : NEG_BIG;
                c[j][e] = s0; c[j][e + 2] = s1v;
                mx0 = fmaxf(mx0, s0); mx1 = fmaxf(mx1, s1v);
            }
        }
        mx0 = fmaxf(mx0, __shfl_xor_sync(0xffffffffu, mx0, 1));
        mx0 = fmaxf(mx0, __shfl_xor_sync(0xffffffffu, mx0, 2));
        mx1 = fmaxf(mx1, __shfl_xor_sync(0xffffffffu, mx1, 1));
        mx1 = fmaxf(mx1, __shfl_xor_sync(0xffffffffu, mx1, 2));
        if ((lane & 3) == 0) {
            hm[r0l * 2 + ch] = mx0;
            hm[(r0l + 8) * 2 + ch] = mx1;
        }
        __syncthreads();

        const float tm0 = fmaxf(hm[r0l * 2], hm[r0l * 2 + 1]);
        const float tm1 = fmaxf(hm[(r0l + 8) * 2], hm[(r0l + 8) * 2 + 1]);
        const float mnew0 = fmaxf(mrow0, tm0), mnew1 = fmaxf(mrow1, tm1);
        const float alpha0 = __expf(mrow0 - mnew0), alpha1 = __expf(mrow1 - mnew1);
        mrow0 = mnew0; mrow1 = mnew1;

        float sum0 = 0.f, sum1 = 0.f;
        #pragma unroll
        for (int j = 0; j < 4; j++) {
            float p00 = __expf(c[j][0] - mnew0), p01 = __expf(c[j][1] - mnew0);
            float p10 = __expf(c[j][2] - mnew1), p11 = __expf(c[j][3] - mnew1);
            sum0 += p00 + p01; sum1 += p10 + p11;
            int nloc = ch * 32 + j * 8 + 2 * (lane & 3);
            int chunk = nloc >> 3;
            uint32_t hi, lo;
            uint32_t off0 = (uint32_t)(r0l * 128 + ((chunk ^ (r0l & 7)) * 16) + (nloc & 7) * 2);
            split2(p00, p01, hi, lo);
            *(uint32_t*)(smc + PHI_OFF + off0) = hi;
            *(uint32_t*)(smc + PLO_OFF + off0) = lo;
            int r1 = r0l + 8;
            uint32_t off1 = (uint32_t)(r1 * 128 + ((chunk ^ (r1 & 7)) * 16) + (nloc & 7) * 2);
            split2(p10, p11, hi, lo);
            *(uint32_t*)(smc + PHI_OFF + off1) = hi;
            *(uint32_t*)(smc + PLO_OFF + off1) = lo;
        }
        sum0 += __shfl_xor_sync(0xffffffffu, sum0, 1);
        sum0 += __shfl_xor_sync(0xffffffffu, sum0, 2);
        sum1 += __shfl_xor_sync(0xffffffffu, sum1, 1);
        sum1 += __shfl_xor_sync(0xffffffffu, sum1, 2);
        if ((lane & 3) == 0) {
            hs[r0l * 2 + ch] = sum0;
            hs[(r0l + 8) * 2 + ch] = sum1;
        }

        // rescale O while sums land
        #pragma unroll
        for (int j = 0; j < 16; j++) {
            O[j][0] *= alpha0; O[j][1] *= alpha0;
            O[j][2] *= alpha1; O[j][3] *= alpha1;
        }
        __syncthreads();

        lrow0 = lrow0 * alpha0 + hs[r0l * 2] + hs[r0l * 2 + 1];
        lrow1 = lrow1 * alpha1 + hs[(r0l + 8) * 2] + hs[(r0l + 8) * 2 + 1];

        // ---- PV GEMM: O[16 rows][128 d] += P[16][64] * V[64][128] ----
        #pragma unroll
        for (int ks = 0; ks < 4; ks++) {
            uint32_t aoff = swz(rg * 16 + (lane & 15), 2 * ks + (lane >> 4), 128);
            uint32_t ph0, ph1, ph2, ph3, pl0, pl1, pl2, pl3;
            ldsm_x4(ph0, ph1, ph2, ph3, smem + PHI_OFF + aoff);
            ldsm_x4(pl0, pl1, pl2, pl3, smem + PLO_OFF + aoff);
            const int vrow = ks * 16 + (lane & 15);
            #pragma unroll
            for (int jp = 0; jp < 8; jp++) {
                uint32_t boff = swz(vrow, ch * 16 + 2 * jp + (lane >> 4), 512);
                uint32_t vh0, vh1, vh2, vh3, vl0, vl1, vl2, vl3;
                ldsm_x4t(vh0, vh1, vh2, vh3, smem + KHI_OFF + boff);
                ldsm_x4t(vl0, vl1, vl2, vl3, smem + KLO_OFF + boff);
                mma16816(O[2 * jp], ph0, ph1, ph2, ph3, vh0, vh1);
                mma16816(O[2 * jp + 1], ph0, ph1, ph2, ph3, vh2, vh3);
                mma16816(O[2 * jp], ph0, ph1, ph2, ph3, vl0, vl1);
                mma16816(O[2 * jp + 1], ph0, ph1, ph2, ph3, vl2, vl3);
                mma16816(O[2 * jp], pl0, pl1, pl2, pl3, vh0, vh1);
                mma16816(O[2 * jp + 1], pl0, pl1, pl2, pl3, vh2, vh3);
            }
        }
    }

    // ---------------- epilogue ----------------
    const int gr0 = m0 + r0l, gr1 = gr0 + 8;
    const float inv0 = (gr0 < L1v) ? (1.f / lrow0) : 0.f;
    const float inv1 = (gr1 < L1v) ? (1.f / lrow1) : 0.f;
    float* orow0 = outTile + r0l * DD + ch * 128 + 2 * (lane & 3);
    float* orow1 = orow0 + 8 * DD;
    #pragma unroll
    for (int j = 0; j < 16; j++) {
        float2 v0; v0.x = O[j][0] * inv0; v0.y = O[j][1] * inv0;
        float2 v1; v1.x = O[j][2] * inv1; v1.y = O[j][3] * inv1;
        *(float2*)(orow0 + j * 8) = v0;
        *(float2*)(orow1 + j * 8) = v1;
    }
}

extern "C" void kernel_launch(void* const* d_in, const int* in_sizes, int n_in,
                              void* d_out, int out_size)
{
    const float* s1 = (const float*)d_in[0];
    const float* s2 = (const float*)d_in[1];
    const float* w  = (const float*)d_in[2];
    const int*   l1 = (const int*)d_in[3];
    const int*   l2 = (const int*)d_in[4];
    float* out = (float*)d_out;

    const int B  = in_sizes[3];
    const int D  = in_sizes[2] / 3;
    const int t1 = in_sizes[0] / (B * D);

    cudaFuncSetAttribute(bidaf_mma, cudaFuncAttributeMaxDynamicSharedMemorySize,
                         SMEM_BYTES);
    dim3 grid(t1 / 64, B);
    bidaf_mma<<<grid, NT, SMEM_BYTES>>>(s1, s2, w, l1, l2, out);
}